// round 13
// baseline (speedup 1.0000x reference)
#include <cuda_runtime.h>
#include <math.h>

// Problem constants (fixed by the dataset)
#define N_NODES 30000
#define E_EDGES 480000
#define E_TOT   (E_EDGES + N_NODES)   // edges + self loops = 510000
#define G_GRAPHS 128
#define MAXF 192
#define SCAN_B 1024
#define SCAN_NB ((N_NODES + SCAN_B - 1) / SCAN_B)

typedef unsigned long long ull;

// ---------------- scratch (static device globals; no allocation) -------------
__device__ float g_x   [N_NODES * MAXF];
__device__ float g_xl  [N_NODES * MAXF];
__device__ float g_xr  [N_NODES * MAXF];
__device__ int   g_deg [N_NODES];
__device__ int   g_rp  [N_NODES + 1];
__device__ int   g_cur [N_NODES];
__device__ int   g_csrc[E_TOT];
__device__ int   g_part[SCAN_NB];
__device__ float g_gs  [G_GRAPHS * 64];
__device__ float g_cnt [G_GRAPHS];

// ---------------- f32x2 helpers ------------------------------------------------
__device__ __forceinline__ ull pack2(float lo, float hi) {
    ull r; asm("mov.b64 %0, {%1, %2};" : "=l"(r) : "f"(lo), "f"(hi)); return r;
}
__device__ __forceinline__ void fma2(ull& acc, ull a, ull b) {
    asm("fma.rn.f32x2 %0, %1, %2, %3;" : "=l"(acc) : "l"(a), "l"(b), "l"(acc));
}

// ---------------- small utility kernels ----------------------------------------
__global__ void k_fill_i(int* __restrict__ p, int v, int n) {
    int i = blockIdx.x * blockDim.x + threadIdx.x;
    if (i < n) p[i] = v;
}
__global__ void k_zero_pool(float* __restrict__ gs, float* __restrict__ cnt) {
    int i = blockIdx.x * blockDim.x + threadIdx.x;
    if (i < G_GRAPHS * 64) gs[i] = 0.f;
    if (i < G_GRAPHS) cnt[i] = 0.f;
}

// ---------------- CSR build (by destination) -----------------------------------
__global__ void k_count(const int* __restrict__ ei, int* __restrict__ deg) {
    int e = blockIdx.x * blockDim.x + threadIdx.x;
    if (e >= E_TOT) return;
    int dst = (e < E_EDGES) ? ei[E_EDGES + e] : (e - E_EDGES);
    atomicAdd(&deg[dst], 1);
}

__global__ void k_scan1(const int* __restrict__ deg, int* __restrict__ part) {
    __shared__ int sm[SCAN_B];
    int i = blockIdx.x * SCAN_B + threadIdx.x;
    sm[threadIdx.x] = (i < N_NODES) ? deg[i] : 0;
    __syncthreads();
    for (int o = SCAN_B / 2; o; o >>= 1) {
        if (threadIdx.x < o) sm[threadIdx.x] += sm[threadIdx.x + o];
        __syncthreads();
    }
    if (threadIdx.x == 0) part[blockIdx.x] = sm[0];
}
__global__ void k_scan2(int* __restrict__ part) {       // warp scan, SCAN_NB <= 32
    int lane = threadIdx.x;
    int v = (lane < SCAN_NB) ? part[lane] : 0;
    int orig = v;
    #pragma unroll
    for (int o = 1; o < 32; o <<= 1) {
        int t = __shfl_up_sync(0xffffffffu, v, o);
        if (lane >= o) v += t;
    }
    if (lane < SCAN_NB) part[lane] = v - orig;          // exclusive
}
__global__ void k_scan3(const int* __restrict__ deg, const int* __restrict__ part,
                        int* __restrict__ rp, int* __restrict__ cur) {
    __shared__ int sm[SCAN_B];
    int i = blockIdx.x * SCAN_B + threadIdx.x;
    int v = (i < N_NODES) ? deg[i] : 0;
    sm[threadIdx.x] = v;
    __syncthreads();
    for (int o = 1; o < SCAN_B; o <<= 1) {
        int t = (threadIdx.x >= o) ? sm[threadIdx.x - o] : 0;
        __syncthreads();
        sm[threadIdx.x] += t;
        __syncthreads();
    }
    int excl = sm[threadIdx.x] - v + part[blockIdx.x];
    if (i < N_NODES) { rp[i] = excl; cur[i] = excl; }
    if (i == N_NODES - 1) rp[N_NODES] = excl + v;
}

__global__ void k_scatter(const int* __restrict__ ei, int* __restrict__ cur,
                          int* __restrict__ csrc) {
    int e = blockIdx.x * blockDim.x + threadIdx.x;
    if (e >= E_TOT) return;
    int src, dst;
    if (e < E_EDGES) { src = ei[e]; dst = ei[E_EDGES + e]; }
    else             { src = dst = e - E_EDGES; }
    int pos = atomicAdd(&cur[dst], 1);
    csrc[pos] = src;
}

// ---------------- row-tiled dual GEMM, f32x2 FMA + LDS.128 ----------------------
template <int K, int M, int ROWS, bool EMB>
__global__ void k_gemm2(const float* __restrict__ X, const int* __restrict__ ids,
                        const float* __restrict__ Wl, const float* __restrict__ bl,
                        const float* __restrict__ Wr, const float* __restrict__ br,
                        float* __restrict__ Yl, float* __restrict__ Yr) {
    constexpr int PAD = ROWS + 4;     // 36: keeps each k-row 16B-aligned (36*4=144)
    constexpr int NP  = ROWS / 2;     // row pairs
    constexpr int NQ  = ROWS / 4;     // row quads
    __shared__ __align__(16) float sxt[K * PAD];
    int row0 = blockIdx.x * ROWS;
    int nr = min(ROWS, N_NODES - row0);
    for (int i = threadIdx.x; i < nr * K; i += M) {
        int r = i / K, k = i - r * K;
        float v = EMB ? X[(size_t)ids[row0 + r] * K + k]
                      : X[(size_t)row0 * K + i];
        sxt[k * PAD + r] = v;
    }
    for (int i = threadIdx.x; i < (ROWS - nr) * K; i += M) {
        int r = nr + i / K, k = i - (i / K) * K;
        sxt[k * PAD + r] = 0.0f;
    }
    __syncthreads();

    int c = threadIdx.x;
    ull al[NP], ar[NP];
    {
        ull bl2 = pack2(bl[c], bl[c]);
        ull br2 = pack2(br[c], br[c]);
        #pragma unroll
        for (int p = 0; p < NP; p++) { al[p] = bl2; ar[p] = br2; }
    }
    #pragma unroll 4
    for (int k = 0; k < K; k++) {
        float wl = Wl[k * M + c], wr = Wr[k * M + c];
        ull wl2 = pack2(wl, wl), wr2 = pack2(wr, wr);
        const float4* rowp = (const float4*)&sxt[k * PAD];
        #pragma unroll
        for (int q = 0; q < NQ; q++) {
            float4 xv = rowp[q];                 // 4 rows, one LDS.128 broadcast
            ull lo = pack2(xv.x, xv.y);
            ull hi = pack2(xv.z, xv.w);
            fma2(al[2 * q],     lo, wl2);
            fma2(ar[2 * q],     lo, wr2);
            fma2(al[2 * q + 1], hi, wl2);
            fma2(ar[2 * q + 1], hi, wr2);
        }
    }
    #pragma unroll
    for (int p = 0; p < NP; p++) {
        float2 ul = *(float2*)&al[p];
        float2 ur = *(float2*)&ar[p];
        int r0 = 2 * p;
        if (r0 < nr) {
            Yl[(size_t)(row0 + r0) * M + c] = ul.x;
            Yr[(size_t)(row0 + r0) * M + c] = ur.x;
        }
        if (r0 + 1 < nr) {
            Yl[(size_t)(row0 + r0 + 1) * M + c] = ul.y;
            Yr[(size_t)(row0 + r0 + 1) * M + c] = ur.y;
        }
    }
}

// ---------------- warp-per-node fused attention (register-resident) -------------
// One warp per dst node; edges processed two at a time (interleaved gathers and
// logit chains for MLP), fused two-edge online-softmax update. No smem/barriers.
template <int H, int C>
__global__ void k_attnw(const float* __restrict__ xl, const float* __restrict__ xr,
                        const float* __restrict__ att, const float* __restrict__ bo,
                        const int* __restrict__ rp, const int* __restrict__ csrc,
                        float* __restrict__ out) {
    constexpr int M   = H * C;
    constexpr int R   = M / 32;     // regs per lane
    constexpr int RPH = C / 32;     // regs per head
    int warp = (blockIdx.x * blockDim.x + threadIdx.x) >> 5;
    int lane = threadIdx.x & 31;
    if (warp >= N_NODES) return;
    int dst = warp;
    int start = rp[dst];
    int deg   = rp[dst + 1] - start;

    float v_att[R], v_xr[R], acc[R];
    #pragma unroll
    for (int k = 0; k < R; k++) {
        int j = k * 32 + lane;
        v_att[k] = att[j];
        v_xr[k]  = xr[(size_t)dst * M + j];
        acc[k]   = 0.f;
    }
    float m[H], den[H];
    #pragma unroll
    for (int h = 0; h < H; h++) { m[h] = -INFINITY; den[h] = 0.f; }

    for (int base = 0; base < deg; base += 32) {
        int nn = min(32, deg - base);
        int myidx = (base + lane < deg) ? csrc[start + base + lane] : 0;

        int e = 0;
        for (; e + 1 < nn; e += 2) {
            int s0 = __shfl_sync(0xffffffffu, myidx, e);
            int s1 = __shfl_sync(0xffffffffu, myidx, e + 1);
            const float* r0 = xl + (size_t)s0 * M;
            const float* r1 = xl + (size_t)s1 * M;
            float x0[R], x1[R], sa[H], sb[H];
            #pragma unroll
            for (int h = 0; h < H; h++) { sa[h] = 0.f; sb[h] = 0.f; }
            #pragma unroll
            for (int k = 0; k < R; k++) {        // interleaved loads -> MLP=2R
                x0[k] = r0[k * 32 + lane];
                x1[k] = r1[k * 32 + lane];
            }
            #pragma unroll
            for (int k = 0; k < R; k++) {
                float u0 = x0[k] + v_xr[k];
                float u1 = x1[k] + v_xr[k];
                u0 = (u0 > 0.f) ? u0 : 0.2f * u0;
                u1 = (u1 > 0.f) ? u1 : 0.2f * u1;
                sa[k / RPH] = fmaf(v_att[k], u0, sa[k / RPH]);
                sb[k / RPH] = fmaf(v_att[k], u1, sb[k / RPH]);
            }
            #pragma unroll
            for (int h = 0; h < H; h++) {        // two independent shfl chains
                #pragma unroll
                for (int o = 16; o; o >>= 1) {
                    sa[h] += __shfl_xor_sync(0xffffffffu, sa[h], o);
                    sb[h] += __shfl_xor_sync(0xffffffffu, sb[h], o);
                }
            }
            float sc[H], p0[H], p1[H];
            #pragma unroll
            for (int h = 0; h < H; h++) {
                float mn = fmaxf(m[h], fmaxf(sa[h], sb[h]));
                sc[h] = __expf(m[h] - mn);       // exp(-inf)=0 first time
                p0[h] = __expf(sa[h] - mn);
                p1[h] = __expf(sb[h] - mn);
                den[h] = den[h] * sc[h] + p0[h] + p1[h];
                m[h] = mn;
            }
            #pragma unroll
            for (int k = 0; k < R; k++) {
                int h = k / RPH;
                acc[k] = fmaf(acc[k], sc[h], fmaf(p0[h], x0[k], p1[h] * x1[k]));
            }
        }
        if (e < nn) {                            // odd tail edge
            int s0 = __shfl_sync(0xffffffffu, myidx, e);
            const float* r0 = xl + (size_t)s0 * M;
            float x0[R], sa[H];
            #pragma unroll
            for (int h = 0; h < H; h++) sa[h] = 0.f;
            #pragma unroll
            for (int k = 0; k < R; k++) {
                x0[k] = r0[k * 32 + lane];
                float u = x0[k] + v_xr[k];
                u = (u > 0.f) ? u : 0.2f * u;
                sa[k / RPH] = fmaf(v_att[k], u, sa[k / RPH]);
            }
            #pragma unroll
            for (int h = 0; h < H; h++) {
                #pragma unroll
                for (int o = 16; o; o >>= 1)
                    sa[h] += __shfl_xor_sync(0xffffffffu, sa[h], o);
            }
            float sc[H], p0[H];
            #pragma unroll
            for (int h = 0; h < H; h++) {
                float mn = fmaxf(m[h], sa[h]);
                sc[h] = __expf(m[h] - mn);
                p0[h] = __expf(sa[h] - mn);
                den[h] = den[h] * sc[h] + p0[h];
                m[h] = mn;
            }
            #pragma unroll
            for (int k = 0; k < R; k++) {
                int h = k / RPH;
                acc[k] = fmaf(acc[k], sc[h], p0[h] * x0[k]);
            }
        }
    }

    #pragma unroll
    for (int k = 0; k < R; k++) {
        int j = k * 32 + lane;
        out[(size_t)dst * M + j] = __fdividef(acc[k], den[k / RPH]) + bo[j];
    }
}

// ---------------- pooling (sorted batch -> run-length local sums) ---------------
__global__ void k_pool2(const float* __restrict__ x, const int* __restrict__ batch,
                        float* __restrict__ gs, float* __restrict__ cnt) {
    int j = threadIdx.x;              // 0..63 feature
    int w = threadIdx.y;              // 0..3
    int i0 = blockIdx.x * 128;
    int iend = min(i0 + 128, N_NODES);
    float acc = 0.f, cn = 0.f;
    int curb = -1;
    for (int i = i0 + w; i < iend; i += 4) {
        int b = batch[i];
        if (b != curb) {
            if (curb >= 0) {
                atomicAdd(&gs[curb * 64 + j], acc);
                if (j == 0) atomicAdd(&cnt[curb], cn);
            }
            curb = b; acc = 0.f; cn = 0.f;
        }
        acc += x[(size_t)i * 64 + j];
        cn += 1.f;
    }
    if (curb >= 0) {
        atomicAdd(&gs[curb * 64 + j], acc);
        if (j == 0) atomicAdd(&cnt[curb], cn);
    }
}

__global__ void k_mlp(const float* __restrict__ gs, const float* __restrict__ cnt,
                      const float* __restrict__ demo,
                      const float* __restrict__ Wc1, const float* __restrict__ bc1,
                      const float* __restrict__ Wc2, const float* __restrict__ bc2,
                      float* __restrict__ out) {
    int g = blockIdx.x * blockDim.x + threadIdx.x;
    if (g >= G_GRAPHS) return;
    float inv = 1.0f / fmaxf(cnt[g], 1.0f);
    float in[69];
    #pragma unroll
    for (int j = 0; j < 64; j++) in[j] = gs[g * 64 + j] * inv;
    #pragma unroll
    for (int j = 0; j < 5; j++) in[64 + j] = demo[g * 5 + j];
    float h[32];
    #pragma unroll
    for (int o = 0; o < 32; o++) {
        float a = bc1[o];
        for (int i = 0; i < 69; i++) a = fmaf(in[i], Wc1[i * 32 + o], a);
        h[o] = fmaxf(a, 0.0f);
    }
    #pragma unroll
    for (int o = 0; o < 2; o++) {
        float a = bc2[o];
        #pragma unroll
        for (int i = 0; i < 32; i++) a = fmaf(h[i], Wc2[i * 2 + o], a);
        out[g * 2 + o] = a;
    }
}

// ---------------- launch --------------------------------------------------------
static inline int ceil_div(int a, int b) { return (a + b - 1) / b; }

extern "C" void kernel_launch(void* const* d_in, const int* in_sizes, int n_in,
                              void* d_out, int out_size) {
    const float* emb  = (const float*)d_in[0];
    const float* Wl0  = (const float*)d_in[1];
    const float* bl0  = (const float*)d_in[2];
    const float* Wr0  = (const float*)d_in[3];
    const float* br0  = (const float*)d_in[4];
    const float* att0 = (const float*)d_in[5];
    const float* bo0  = (const float*)d_in[6];
    const float* Wl1  = (const float*)d_in[7];
    const float* bl1  = (const float*)d_in[8];
    const float* Wr1  = (const float*)d_in[9];
    const float* br1  = (const float*)d_in[10];
    const float* att1 = (const float*)d_in[11];
    const float* bo1  = (const float*)d_in[12];
    const float* Wl1b = bl1; (void)Wl1b;
    const float* Wl2  = (const float*)d_in[13];
    const float* bl2  = (const float*)d_in[14];
    const float* Wr2  = (const float*)d_in[15];
    const float* br2  = (const float*)d_in[16];
    const float* att2 = (const float*)d_in[17];
    const float* bo2  = (const float*)d_in[18];
    const float* Wc1  = (const float*)d_in[19];
    const float* bc1  = (const float*)d_in[20];
    const float* Wc2  = (const float*)d_in[21];
    const float* bc2  = (const float*)d_in[22];
    const float* demo = (const float*)d_in[23];
    const int*   ids  = (const int*)d_in[24];
    const int*   ei   = (const int*)d_in[25];
    const int*   batch= (const int*)d_in[26];
    float* out = (float*)d_out;

    float *px, *pxl, *pxr, *pgs, *pcnt;
    int *pdeg, *prp, *pcur, *pcsrc, *ppart;
    cudaGetSymbolAddress((void**)&px,    g_x);
    cudaGetSymbolAddress((void**)&pxl,   g_xl);
    cudaGetSymbolAddress((void**)&pxr,   g_xr);
    cudaGetSymbolAddress((void**)&pdeg,  g_deg);
    cudaGetSymbolAddress((void**)&prp,   g_rp);
    cudaGetSymbolAddress((void**)&pcur,  g_cur);
    cudaGetSymbolAddress((void**)&pcsrc, g_csrc);
    cudaGetSymbolAddress((void**)&ppart, g_part);
    cudaGetSymbolAddress((void**)&pgs,   g_gs);
    cudaGetSymbolAddress((void**)&pcnt,  g_cnt);

    const int T = 256;
    const int WARPS_PER_BLOCK = 8;                       // 256 threads
    const int ATT_GRID = ceil_div(N_NODES, WARPS_PER_BLOCK);

    // CSR by destination (shared by all three layers)
    k_fill_i<<<ceil_div(N_NODES, T), T>>>(pdeg, 0, N_NODES);
    k_count<<<ceil_div(E_TOT, T), T>>>(ei, pdeg);
    k_scan1<<<SCAN_NB, SCAN_B>>>(pdeg, ppart);
    k_scan2<<<1, 32>>>(ppart);
    k_scan3<<<SCAN_NB, SCAN_B>>>(pdeg, ppart, prp, pcur);
    k_scatter<<<ceil_div(E_TOT, T), T>>>(ei, pcur, pcsrc);

    // layer 0: emb-gathered 16 -> 3 heads x 32   (embedding lookup fused)
    k_gemm2<16, 96, 32, true><<<ceil_div(N_NODES, 32), 96>>>(emb, ids, Wl0, bl0, Wr0, br0, pxl, pxr);
    k_attnw<3, 32><<<ATT_GRID, T>>>(pxl, pxr, att0, bo0, prp, pcsrc, px);

    // layer 1: 96 -> 2 heads x 96
    k_gemm2<96, 192, 32, false><<<ceil_div(N_NODES, 32), 192>>>(px, nullptr, Wl1, bl1, Wr1, br1, pxl, pxr);
    k_attnw<2, 96><<<ATT_GRID, T>>>(pxl, pxr, att1, bo1, prp, pcsrc, px);

    // layer 2: 192 -> 1 head x 64
    k_gemm2<192, 64, 32, false><<<ceil_div(N_NODES, 32), 64>>>(px, nullptr, Wl2, bl2, Wr2, br2, pxl, pxr);
    k_attnw<1, 64><<<ATT_GRID, T>>>(pxl, pxr, att2, bo2, prp, pcsrc, px);

    // global mean pool + MLP head
    k_zero_pool<<<ceil_div(G_GRAPHS * 64, T), T>>>(pgs, pcnt);
    dim3 pb(64, 4);
    k_pool2<<<ceil_div(N_NODES, 128), pb>>>(px, batch, pgs, pcnt);
    k_mlp<<<1, G_GRAPHS>>>(pgs, pcnt, demo, Wc1, bc1, Wc2, bc2, out);
}